// round 8
// baseline (speedup 1.0000x reference)
#include <cuda_runtime.h>
#include <cuda_fp16.h>
#include <cuda_bf16.h>
#include <cstdint>

#define BB 128
#define LL 100
#define DD 512
#define EE 8
#define K0 900
#define KP 960
#define KC 64
#define NCH 15
#define OUTM (BB*LL*DD)

// scratch (device globals; no allocation allowed)
__device__ float  g_gates[BB*EE];
__device__ __half g_wh[(size_t)BB*DD*KP];   // mixed weights hi, [b][n][k], 126MB
__device__ __half g_wl[(size_t)BB*DD*KP];   // mixed weights lo

__device__ __forceinline__ uint32_t su32(const void* p){
  uint32_t a;
  asm("{ .reg .u64 t; cvta.to.shared.u64 t, %1; cvt.u32.u64 %0, t; }":"=r"(a):"l"(p));
  return a;
}
// swizzled byte offset inside a [rows][64 halves] tile (128B rows, SW over 16B groups)
__device__ __forceinline__ int boff(int r,int c){
  return r*128 + ((((c>>3)^(r&7))<<4) | ((c&7)<<1));
}
#define LDM4(r0,r1,r2,r3,a) \
  asm volatile("ldmatrix.sync.aligned.m8n8.x4.shared.b16 {%0,%1,%2,%3},[%4];" \
    :"=r"(r0),"=r"(r1),"=r"(r2),"=r"(r3):"r"(a))
#define MMA(c,a,b0,b1) \
  asm volatile("mma.sync.aligned.m16n8k16.row.col.f32.f16.f16.f32 " \
    "{%0,%1,%2,%3},{%4,%5,%6,%7},{%8,%9},{%0,%1,%2,%3};" \
    :"+f"((c)[0]),"+f"((c)[1]),"+f"((c)[2]),"+f"((c)[3]) \
    :"r"((a)[0]),"r"((a)[1]),"r"((a)[2]),"r"((a)[3]),"r"(b0),"r"(b1))

__device__ __forceinline__ float bf16r(float x){
  return __bfloat162float(__float2bfloat16_rn(x));
}

// ------------- kernel 1: identify logits/masks, gates + guide loss -----------
__global__ void k_gates(const float* __restrict__ c0, const float* __restrict__ c1,
                        float* __restrict__ out, int tail){
  __shared__ float red[BB];
  __shared__ int flag;           // 1 => c0 is the int mask
  int b = threadIdx.x;
  if(b==0) flag = 1;
  __syncthreads();
  {
    const unsigned* u0 = (const unsigned*)c0;
    int ok = 1;
#pragma unroll
    for(int e=0;e<EE;e++) if(u0[b*EE+e] > 1u) ok = 0;
    if(!ok) atomicAnd(&flag, 0);
  }
  __syncthreads();
  const float* logits = flag ? c1 : c0;
  const int*   masks  = flag ? (const int*)c0 : (const int*)c1;

  float v[EE]; float mx = -1e30f;
#pragma unroll
  for(int e=0;e<EE;e++){ v[e]=logits[b*EE+e]; mx=fmaxf(mx,v[e]); }
  float s=0.f;
#pragma unroll
  for(int e=0;e<EE;e++){ v[e]=expf(v[e]-mx); s+=v[e]; }
  float inv=1.f/s, gs=0.f;
#pragma unroll
  for(int e=0;e<EE;e++){ float r=v[e]*inv*((masks[b*EE+e]==1)?1.f:0.f); v[e]=r; gs+=r; }
  float rn=1.f/(gs+1e-9f);
#pragma unroll
  for(int e=0;e<EE;e++) g_gates[b*EE+e]=v[e]*rn;
  red[b]=gs;
  __syncthreads();
  if(b==0){
    float t=0.f;
    for(int i=0;i<BB;i++) t+=red[i];
    float loss = 1.f - t/128.f; loss*=loss;
    for(int i=0;i<tail;i++) out[OUTM+i]=loss;
  }
}

// ------------- kernel 2: Wmix[b][n][k] = sum_e g[b,e] W[e,k,n], fp16 hi/lo ---
__global__ __launch_bounds__(256) void k_mix(const float* __restrict__ W){
  __shared__ float wt[EE][32][33];
  __shared__ float gsh[BB*EE];
  int tid = threadIdx.x;
  int kb = blockIdx.x*32, nb = blockIdx.y*32;
  for(int i=tid;i<BB*EE;i+=256) gsh[i]=g_gates[i];
  for(int i=tid;i<EE*1024;i+=256){
    int e=i>>10, k2=(i>>5)&31, n2=i&31;
    int k=kb+k2;
    wt[e][k2][n2] = (k<K0) ? W[((size_t)e*K0+k)*DD + nb+n2] : 0.f;
  }
  __syncthreads();
  int k2 = tid&31, ng = tid>>5;           // thread: k=kb+k2, n=nb+ng+8p
  float wr[EE][4];
#pragma unroll
  for(int e=0;e<EE;e++)
#pragma unroll
    for(int p=0;p<4;p++) wr[e][p]=wt[e][k2][ng+p*8];
  for(int b=0;b<BB;b++){
    float g[EE];
#pragma unroll
    for(int e=0;e<EE;e++) g[e]=gsh[b*EE+e];
    size_t bo=(size_t)b*DD*KP;
#pragma unroll
    for(int p=0;p<4;p++){
      float acc=0.f;
#pragma unroll
      for(int e=0;e<EE;e++) acc=fmaf(g[e],wr[e][p],acc);
      size_t a = bo + (size_t)(nb+ng+p*8)*KP + (kb+k2);
      __half h=__float2half_rn(acc);
      g_wh[a]=h;
      g_wl[a]=__float2half_rn(acc-__half2float(h));
    }
  }
}

// ------------- kernel 3: per-batch split-fp16 GEMM ---------------------------
// grid (4 n-tiles, 128 batches), 256 threads (8 warps, warp w -> rows 16w..16w+15)
extern __shared__ char smdyn[];
__global__ __launch_bounds__(256,2) void k_gemm(const float* __restrict__ x,
        const float* __restrict__ bias, float* __restrict__ out){
  int nt = blockIdx.x, b = blockIdx.y;
  char* sAh = smdyn;          char* sAl = smdyn+16384;
  char* sBh = smdyn+32768;    char* sBl = smdyn+49152;
  float* sBias = (float*)(smdyn+65536);
  int tid = threadIdx.x, w = tid>>5, l = tid&31;
  if(tid<128){
    float s=0.f;
#pragma unroll
    for(int e=0;e<EE;e++) s += g_gates[b*EE+e]*bias[e*DD + nt*128 + tid];
    sBias[tid]=s;
  }
  float cc[16][4];
#pragma unroll
  for(int j=0;j<16;j++){ cc[j][0]=0;cc[j][1]=0;cc[j][2]=0;cc[j][3]=0; }
  const float*  xb = x + (size_t)b*LL*K0;
  const __half* bh = g_wh + ((size_t)b*DD + nt*128)*KP;
  const __half* bl = g_wl + ((size_t)b*DD + nt*128)*KP;
  uint32_t uAh=su32(sAh), uAl=su32(sAl), uBh=su32(sBh), uBl=su32(sBl);

  for(int ci=0; ci<NCH; ci++){
    int kb = ci*KC;
    __syncthreads();
    // A tile (fp32 x -> hi/lo fp16), rows>=100 and k>=900 zero-padded
#pragma unroll
    for(int t=0;t<8;t++){
      int q = tid + t*256;
      int r = q>>4, c = (q&15)<<2;
      float4 v = make_float4(0.f,0.f,0.f,0.f);
      if(r<LL && kb+c<K0) v = *(const float4*)(xb + r*K0 + kb + c);
      __half h0=__float2half_rn(v.x), h1=__float2half_rn(v.y);
      __half h2=__float2half_rn(v.z), h3=__float2half_rn(v.w);
      __half q0=__float2half_rn(v.x-__half2float(h0)), q1=__float2half_rn(v.y-__half2float(h1));
      __half q2=__float2half_rn(v.z-__half2float(h2)), q3=__float2half_rn(v.w-__half2float(h3));
      int o = boff(r,c);
      *(__half2*)(sAh+o)   = __halves2half2(h0,h1);
      *(__half2*)(sAh+o+4) = __halves2half2(h2,h3);
      *(__half2*)(sAl+o)   = __halves2half2(q0,q1);
      *(__half2*)(sAl+o+4) = __halves2half2(q2,q3);
    }
    // B tiles (fp16 hi/lo planes)
#pragma unroll
    for(int t=0;t<4;t++){
      int q = tid + t*256;
      int n = q>>3, c = (q&7)<<3;
      size_t go = (size_t)n*KP + kb + c;
      int o = boff(n,c);
      *(uint4*)(sBh+o) = *(const uint4*)(bh+go);
      *(uint4*)(sBl+o) = *(const uint4*)(bl+go);
    }
    __syncthreads();
#pragma unroll
    for(int ks4=0;ks4<4;ks4++){
      int ks = ks4<<4;
      uint32_t Ah[4], Al[4];
      int ar = (w<<4) + (l&15);
      int ao = boff(ar, ks + ((l>>4)<<3));
      LDM4(Ah[0],Ah[1],Ah[2],Ah[3], uAh+ao);
      LDM4(Al[0],Al[1],Al[2],Al[3], uAl+ao);
#pragma unroll
      for(int j=0;j<8;j++){
        int bn = (j<<4) + (l&7) + ((l&16)?8:0);
        int bo = boff(bn, ks + (l&8));
        uint32_t Bh[4], Bl[4];
        LDM4(Bh[0],Bh[1],Bh[2],Bh[3], uBh+bo);
        LDM4(Bl[0],Bl[1],Bl[2],Bl[3], uBl+bo);
        MMA(cc[2*j],  Ah,Bh[0],Bh[1]); MMA(cc[2*j],  Al,Bh[0],Bh[1]); MMA(cc[2*j],  Ah,Bl[0],Bl[1]);
        MMA(cc[2*j+1],Ah,Bh[2],Bh[3]); MMA(cc[2*j+1],Al,Bh[2],Bh[3]); MMA(cc[2*j+1],Ah,Bl[2],Bl[3]);
      }
    }
  }
  // epilogue: +bias, bf16-round, store as f32, rows<100 only
  int r0 = (w<<4) + (l>>2);
#pragma unroll
  for(int j=0;j<16;j++){
    int nl = (j<<3) + ((l&3)<<1);
    int n  = nt*128 + nl;
    float b0 = sBias[nl], b1 = sBias[nl+1];
    if(r0 < LL){
      float2 v = make_float2(bf16r(cc[j][0]+b0), bf16r(cc[j][1]+b1));
      *(float2*)(out + (size_t)(b*LL + r0)*DD + n) = v;
    }
    if(r0+8 < LL){
      float2 v = make_float2(bf16r(cc[j][2]+b0), bf16r(cc[j][3]+b1));
      *(float2*)(out + (size_t)(b*LL + r0+8)*DD + n) = v;
    }
  }
}

extern "C" void kernel_launch(void* const* d_in, const int* in_sizes, int n_in,
                              void* d_out, int out_size){
  // Identify inputs by element count (robust to metadata ordering):
  // x: 11,520,000   W: 3,686,400   b: 4096   logits/masks: 1024 each
  const float* x = nullptr; const float* W = nullptr; const float* bias = nullptr;
  const float* c0 = nullptr; const float* c1 = nullptr;
  for(int i=0;i<n_in;i++){
    int s = in_sizes[i];
    if(s == BB*LL*3*300)      x    = (const float*)d_in[i];
    else if(s == EE*K0*DD)    W    = (const float*)d_in[i];
    else if(s == EE*DD)       bias = (const float*)d_in[i];
    else if(s == BB*EE){ if(!c0) c0 = (const float*)d_in[i]; else c1 = (const float*)d_in[i]; }
  }
  float* out = (float*)d_out;
  int tail = out_size - OUTM; if(tail < 0) tail = 0;
  cudaFuncSetAttribute(k_gemm, cudaFuncAttributeMaxDynamicSharedMemorySize, 66048);
  k_gates<<<1,BB>>>(c0, c1, out, tail);
  k_mix<<<dim3(KP/32, DD/32), 256>>>(W);
  k_gemm<<<dim3(4,BB), 256, 66048>>>(x, bias, out);
}

// round 10
// speedup vs baseline: 1.5507x; 1.5507x over previous
#include <cuda_runtime.h>
#include <cuda_fp16.h>
#include <cuda_bf16.h>
#include <cstdint>

#define BB 128
#define LL 100
#define DD 512
#define EE 8
#define K0 900
#define KP 960
#define KC 64
#define NCH 15
#define OUTM (BB*LL*DD)

// scratch (device globals; no allocation allowed)
__device__ float  g_gates[BB*EE];
__device__ __half g_wh[(size_t)BB*DD*KP];   // mixed weights hi, [b][n][k], 126MB
__device__ __half g_wl[(size_t)BB*DD*KP];   // mixed weights lo

__device__ __forceinline__ uint32_t su32(const void* p){
  uint32_t a;
  asm("{ .reg .u64 t; cvta.to.shared.u64 t, %1; cvt.u32.u64 %0, t; }":"=r"(a):"l"(p));
  return a;
}
// swizzled byte offset inside a [rows][64 halves] tile (128B rows, SW over 16B groups)
__device__ __forceinline__ int boff(int r,int c){
  return r*128 + ((((c>>3)^(r&7))<<4) | ((c&7)<<1));
}
#define LDM4(r0,r1,r2,r3,a) \
  asm volatile("ldmatrix.sync.aligned.m8n8.x4.shared.b16 {%0,%1,%2,%3},[%4];" \
    :"=r"(r0),"=r"(r1),"=r"(r2),"=r"(r3):"r"(a))
#define MMA(c,a,b0,b1) \
  asm volatile("mma.sync.aligned.m16n8k16.row.col.f32.f16.f16.f32 " \
    "{%0,%1,%2,%3},{%4,%5,%6,%7},{%8,%9},{%0,%1,%2,%3};" \
    :"+f"((c)[0]),"+f"((c)[1]),"+f"((c)[2]),"+f"((c)[3]) \
    :"r"((a)[0]),"r"((a)[1]),"r"((a)[2]),"r"((a)[3]),"r"(b0),"r"(b1))

__device__ __forceinline__ void cpa16(uint32_t dst, const __half* src){
  unsigned long long g = __cvta_generic_to_global((const void*)src);
  asm volatile("cp.async.cg.shared.global [%0], [%1], 16;" :: "r"(dst), "l"(g));
}
#define CP_COMMIT() asm volatile("cp.async.commit_group;":::"memory")
#define CP_WAIT1()  asm volatile("cp.async.wait_group 1;":::"memory")
#define CP_WAIT0()  asm volatile("cp.async.wait_group 0;":::"memory")

__device__ __forceinline__ float bf16r(float x){
  return __bfloat162float(__float2bfloat16_rn(x));
}

// ------------- kernel 1: identify logits/masks, gates + guide loss -----------
__global__ void k_gates(const float* __restrict__ c0, const float* __restrict__ c1,
                        float* __restrict__ out, int tail){
  __shared__ float red[BB];
  __shared__ int flag;           // 1 => c0 is the int mask
  int b = threadIdx.x;
  if(b==0) flag = 1;
  __syncthreads();
  {
    const unsigned* u0 = (const unsigned*)c0;
    int ok = 1;
#pragma unroll
    for(int e=0;e<EE;e++) if(u0[b*EE+e] > 1u) ok = 0;
    if(!ok) atomicAnd(&flag, 0);
  }
  __syncthreads();
  const float* logits = flag ? c1 : c0;
  const int*   masks  = flag ? (const int*)c0 : (const int*)c1;

  float v[EE]; float mx = -1e30f;
#pragma unroll
  for(int e=0;e<EE;e++){ v[e]=logits[b*EE+e]; mx=fmaxf(mx,v[e]); }
  float s=0.f;
#pragma unroll
  for(int e=0;e<EE;e++){ v[e]=expf(v[e]-mx); s+=v[e]; }
  float inv=1.f/s, gs=0.f;
#pragma unroll
  for(int e=0;e<EE;e++){ float r=v[e]*inv*((masks[b*EE+e]==1)?1.f:0.f); v[e]=r; gs+=r; }
  float rn=1.f/(gs+1e-9f);
#pragma unroll
  for(int e=0;e<EE;e++) g_gates[b*EE+e]=v[e]*rn;
  red[b]=gs;
  __syncthreads();
  if(b==0){
    float t=0.f;
    for(int i=0;i<BB;i++) t+=red[i];
    float loss = 1.f - t/128.f; loss*=loss;
    for(int i=0;i<tail;i++) out[OUTM+i]=loss;
  }
}

// ------------- kernel 2: Wmix[b][n][k] = sum_e g[b,e] W[e,k,n], fp16 hi/lo ---
// grid (4 k-chunks of 256, 64 n-chunks of 8), 256 threads = 8 warps.
// warp w -> n-row nb+w; lane l -> k-octet kb+8l. Stores: 32 lanes x 16B = 512B
// fully coalesced per plane.
__global__ __launch_bounds__(256) void k_mix(const float* __restrict__ W){
  __shared__ float wt[EE][8][264];   // [e][n][k 256 + pad]
  __shared__ float gsh[BB*EE];
  int tid = threadIdx.x;
  int kb = blockIdx.x*256, nb = blockIdx.y*8;
  for(int i=tid;i<BB*EE;i+=256) gsh[i]=g_gates[i];
  for(int i=tid;i<EE*256*8;i+=256){
    int e=i>>11, k2=(i>>3)&255, n2=i&7;
    int k=kb+k2;
    wt[e][n2][k2] = (k<K0) ? W[((size_t)e*K0+k)*DD + nb+n2] : 0.f;
  }
  __syncthreads();
  int w = tid>>5, l = tid&31;
  int ko = l*8;
  bool act = (kb + ko) < KP;         // kb=768 chunk: lanes 0..23 only
  float wr[EE][8];
#pragma unroll
  for(int e=0;e<EE;e++){
    *(float4*)&wr[e][0] = *(float4*)&wt[e][w][ko];
    *(float4*)&wr[e][4] = *(float4*)&wt[e][w][ko+4];
  }
  size_t base = (size_t)(nb+w)*KP + kb + ko;
  for(int b=0;b<BB;b++){
    float g[EE];
    *(float4*)&g[0] = *(float4*)&gsh[b*EE];
    *(float4*)&g[4] = *(float4*)&gsh[b*EE+4];
    float acc[8];
#pragma unroll
    for(int j=0;j<8;j++){
      float a = 0.f;
#pragma unroll
      for(int e=0;e<EE;e++) a = fmaf(g[e], wr[e][j], a);
      acc[j]=a;
    }
    if(act){
      __half2 hh[4], ll[4];
#pragma unroll
      for(int j=0;j<4;j++){
        __half h0=__float2half_rn(acc[2*j]), h1=__float2half_rn(acc[2*j+1]);
        hh[j]=__halves2half2(h0,h1);
        ll[j]=__halves2half2(__float2half_rn(acc[2*j]  -__half2float(h0)),
                             __float2half_rn(acc[2*j+1]-__half2float(h1)));
      }
      size_t a0 = (size_t)b*DD*KP + base;
      *(uint4*)(g_wh+a0) = *(uint4*)hh;
      *(uint4*)(g_wl+a0) = *(uint4*)ll;
    }
  }
}

// ------------- kernel 3: per-batch split-fp16 GEMM, cp.async B pipeline ------
// grid (4 n-tiles, 128 batches), 256 threads (8 warps, warp w -> rows 16w..16w+15)
// smem: sAh 0 | sAl 16K | sBh0 32K | sBl0 48K | sBh1 64K | sBl1 80K | bias 96K
extern __shared__ char smdyn[];
__global__ __launch_bounds__(256,2) void k_gemm(const float* __restrict__ x,
        const float* __restrict__ bias, float* __restrict__ out){
  int nt = blockIdx.x, b = blockIdx.y;
  float* sBias = (float*)(smdyn+98304);
  int tid = threadIdx.x, w = tid>>5, l = tid&31;
  if(tid<128){
    float s=0.f;
#pragma unroll
    for(int e=0;e<EE;e++) s += g_gates[b*EE+e]*bias[e*DD + nt*128 + tid];
    sBias[tid]=s;
  }
  float cc[16][4];
#pragma unroll
  for(int j=0;j<16;j++){ cc[j][0]=0;cc[j][1]=0;cc[j][2]=0;cc[j][3]=0; }
  const float*  xb = x + (size_t)b*LL*K0;
  const __half* bh = g_wh + ((size_t)b*DD + nt*128)*KP;
  const __half* bl = g_wl + ((size_t)b*DD + nt*128)*KP;
  uint32_t uAh=su32(smdyn), uAl=su32(smdyn+16384);
  uint32_t uB[2][2] = {{su32(smdyn+32768), su32(smdyn+49152)},
                       {su32(smdyn+65536), su32(smdyn+81920)}};

  // prologue: async B chunk 0 -> buffer 0
  {
#pragma unroll
    for(int t=0;t<4;t++){
      int q = tid + t*256;
      int n = q>>3, c = (q&7)<<3;
      size_t go = (size_t)n*KP + c;
      int o = boff(n,c);
      cpa16(uB[0][0]+o, bh+go);
      cpa16(uB[0][1]+o, bl+go);
    }
    CP_COMMIT();
  }

  for(int ci=0; ci<NCH; ci++){
    int kb = ci*KC, cur = ci&1;
    __syncthreads();                     // previous compute done (smem reusable)
    // A tile for chunk ci (fp32 x -> hi/lo fp16), rows>=100 / k>=900 zero-pad
#pragma unroll
    for(int t=0;t<8;t++){
      int q = tid + t*256;
      int r = q>>4, c = (q&15)<<2;
      float4 v = make_float4(0.f,0.f,0.f,0.f);
      if(r<LL && kb+c<K0) v = *(const float4*)(xb + r*K0 + kb + c);
      __half h0=__float2half_rn(v.x), h1=__float2half_rn(v.y);
      __half h2=__float2half_rn(v.z), h3=__float2half_rn(v.w);
      __half q0=__float2half_rn(v.x-__half2float(h0)), q1=__float2half_rn(v.y-__half2float(h1));
      __half q2=__float2half_rn(v.z-__half2float(h2)), q3=__float2half_rn(v.w-__half2float(h3));
      int o = boff(r,c);
      *(__half2*)(smdyn+o)         = __halves2half2(h0,h1);
      *(__half2*)(smdyn+o+4)       = __halves2half2(h2,h3);
      *(__half2*)(smdyn+16384+o)   = __halves2half2(q0,q1);
      *(__half2*)(smdyn+16384+o+4) = __halves2half2(q2,q3);
    }
    // async B for chunk ci+1 into the other buffer, then drain chunk ci's group
    if(ci < NCH-1){
      int kb2 = kb + KC;
#pragma unroll
      for(int t=0;t<4;t++){
        int q = tid + t*256;
        int n = q>>3, c = (q&7)<<3;
        size_t go = (size_t)n*KP + kb2 + c;
        int o = boff(n,c);
        cpa16(uB[cur^1][0]+o, bh+go);
        cpa16(uB[cur^1][1]+o, bl+go);
      }
      CP_COMMIT();
      CP_WAIT1();                        // chunk ci's B resident
    } else {
      CP_WAIT0();
    }
    __syncthreads();
    uint32_t uBh = uB[cur][0], uBl = uB[cur][1];
#pragma unroll
    for(int ks4=0;ks4<4;ks4++){
      int ks = ks4<<4;
      uint32_t Ah[4], Al[4];
      int ar = (w<<4) + (l&15);
      int ao = boff(ar, ks + ((l>>4)<<3));
      LDM4(Ah[0],Ah[1],Ah[2],Ah[3], uAh+ao);
      LDM4(Al[0],Al[1],Al[2],Al[3], uAl+ao);
#pragma unroll
      for(int j=0;j<8;j++){
        int bn = (j<<4) + (l&7) + ((l&16)?8:0);
        int bo = boff(bn, ks + (l&8));
        uint32_t Bh[4], Bl[4];
        LDM4(Bh[0],Bh[1],Bh[2],Bh[3], uBh+bo);
        LDM4(Bl[0],Bl[1],Bl[2],Bl[3], uBl+bo);
        MMA(cc[2*j],  Ah,Bh[0],Bh[1]); MMA(cc[2*j],  Al,Bh[0],Bh[1]); MMA(cc[2*j],  Ah,Bl[0],Bl[1]);
        MMA(cc[2*j+1],Ah,Bh[2],Bh[3]); MMA(cc[2*j+1],Al,Bh[2],Bh[3]); MMA(cc[2*j+1],Ah,Bl[2],Bl[3]);
      }
    }
  }
  // epilogue: +bias, bf16-round, store as f32, rows<100 only
  int r0 = (w<<4) + (l>>2);
#pragma unroll
  for(int j=0;j<16;j++){
    int nl = (j<<3) + ((l&3)<<1);
    int n  = nt*128 + nl;
    float b0 = sBias[nl], b1 = sBias[nl+1];
    if(r0 < LL){
      float2 v = make_float2(bf16r(cc[j][0]+b0), bf16r(cc[j][1]+b1));
      *(float2*)(out + (size_t)(b*LL + r0)*DD + n) = v;
    }
    if(r0+8 < LL){
      float2 v = make_float2(bf16r(cc[j][2]+b0), bf16r(cc[j][3]+b1));
      *(float2*)(out + (size_t)(b*LL + r0+8)*DD + n) = v;
    }
  }
}

extern "C" void kernel_launch(void* const* d_in, const int* in_sizes, int n_in,
                              void* d_out, int out_size){
  // Identify inputs by element count (robust to metadata ordering):
  // x: 11,520,000   W: 3,686,400   b: 4096   logits/masks: 1024 each
  const float* x = nullptr; const float* W = nullptr; const float* bias = nullptr;
  const float* c0 = nullptr; const float* c1 = nullptr;
  for(int i=0;i<n_in;i++){
    int s = in_sizes[i];
    if(s == BB*LL*3*300)      x    = (const float*)d_in[i];
    else if(s == EE*K0*DD)    W    = (const float*)d_in[i];
    else if(s == EE*DD)       bias = (const float*)d_in[i];
    else if(s == BB*EE){ if(!c0) c0 = (const float*)d_in[i]; else c1 = (const float*)d_in[i]; }
  }
  float* out = (float*)d_out;
  int tail = out_size - OUTM; if(tail < 0) tail = 0;
  cudaFuncSetAttribute(k_gemm, cudaFuncAttributeMaxDynamicSharedMemorySize, 98816);
  k_gates<<<1,BB>>>(c0, c1, out, tail);
  k_mix<<<dim3(4,64), 256>>>(W);
  k_gemm<<<dim3(4,BB), 256, 98816>>>(x, bias, out);
}